// round 16
// baseline (speedup 1.0000x reference)
#include <cuda_runtime.h>

#define NN 64
#define SS 60
#define GG 180
#define BATCH 512
#define SEX 10
#define ROWS 8
#define NT 512
#define NBG (BATCH / ROWS)   // 64
#define NACT 5
#define NROLE 7
#define OO 8
#define II 8

// ---- phase-1 shared memory layout (float offsets) ----
#define OFF_WIH  0          // 180*60
#define OFF_BIH  10800      // 180
#define OFF_BHH  10980      // 180 [g*60+o]
#define OFF_BP   11160      // 60
#define OFF_HAS  11220      // [b][64] = 512
#define OFF_MASK 11732      // 64 ull = 128 floats (8B aligned)
#define OFF_NEED 11860      // 64
#define OFF_WUH  11924      // 7*60 = 420
#define OFF_HBS0 12344      // H ping [b][64] = 512
#define OFF_HBS1 12856      // H pong [b][64] = 512
#define OFF_HSB0 13368      // H ping [o][9] padded = 540
#define OFF_HSB1 13908      // H pong [o][9] padded = 540
#define OFF_S    14448      // [gate][b*60+o] = 4*480 = 1920
#define OFF_RHO  16368      // [o][8] = 480 (16B aligned)
#define OFF_ZI   16848      // [b][10] = 80
#define OFF_DZI  16928      // 80
#define SMEM_FLOATS 17008
#define SMEM_BYTES (SMEM_FLOATS * 4)

// ---- global scratch ----
// gi layout: [node][bg][gate][o][8 rows]
__device__ float g_gi_f[(size_t)NN * NBG * 3 * SS * 8];
__device__ float g_gi_b[(size_t)NN * NBG * 3 * SS * 8];
__device__ float g_alpha_f[(size_t)BATCH * SS];
__device__ float g_alpha_b[(size_t)BATCH * SS];
__device__ float g_psi_f[(size_t)BATCH * NROLE * NN];
__device__ float g_psi_b[(size_t)BATCH * NROLE * NN];

__device__ __forceinline__ float sigm(float x) {
    return __fdividef(1.f, 1.f + __expf(-x));
}
__device__ __forceinline__ float tanh_f(float x) {
    float e = __expf(2.f * x);
    return 1.f - __fdividef(2.f, e + 1.f);
}
__device__ __forceinline__ void fma2(unsigned long long& d, unsigned long long a,
                                     unsigned long long b) {
    asm("fma.rn.f32x2 %0, %1, %2, %0;" : "+l"(d) : "l"(a), "l"(b));
}
__device__ __forceinline__ unsigned long long splat2(float w) {
    unsigned long long r;
    asm("mov.b64 %0, {%1, %1};" : "=l"(r) : "f"(w));
    return r;
}
__device__ __forceinline__ float lo32(unsigned long long v) {
    return __uint_as_float((unsigned)v);
}
__device__ __forceinline__ float hi32(unsigned long long v) {
    return __uint_as_float((unsigned)(v >> 32));
}

// One GRU edge step for 8 batch rows. 12 GEMM warps (gate x half x rowgroup),
// warps 12-15 prestage z/dz for target loadNode (>=0 only on first edge).
__device__ __forceinline__ void gru_step(int node, const float* gi4, bool& hz,
                                         int bg, bool gemmActive, int g, int o, int rg,
                                         const unsigned long long* wp,
                                         int curBS, int nxtBS, int nxtSB,
                                         int loadNode, const float* z, const float* dz,
                                         int row0)
{
    extern __shared__ float sm[];
    const int t = threadIdx.x;
    if (t < 384) {
        if (gemmActive) {
            const float4 gi = *(const float4*)(gi4 +
                ((((size_t)node * NBG + bg) * 3 + g) * SS + o) * 8 + rg * 4);
            unsigned long long acc0 = 0, acc1 = 0, acc2 = 0, acc3 = 0;
            if (!hz) {
                const int hb = curBS + rg * 256;
#pragma unroll
                for (int q = 0; q < 15; q++) {
                    ulonglong2 h0 = *(const ulonglong2*)&sm[hb + 0 * 64 + 4 * q];
                    ulonglong2 h1 = *(const ulonglong2*)&sm[hb + 1 * 64 + 4 * q];
                    ulonglong2 h2 = *(const ulonglong2*)&sm[hb + 2 * 64 + 4 * q];
                    ulonglong2 h3 = *(const ulonglong2*)&sm[hb + 3 * 64 + 4 * q];
                    fma2(acc0, wp[2 * q], h0.x); fma2(acc0, wp[2 * q + 1], h0.y);
                    fma2(acc1, wp[2 * q], h1.x); fma2(acc1, wp[2 * q + 1], h1.y);
                    fma2(acc2, wp[2 * q], h2.x); fma2(acc2, wp[2 * q + 1], h2.y);
                    fma2(acc3, wp[2 * q], h3.x); fma2(acc3, wp[2 * q + 1], h3.y);
                }
            }
            float bh = sm[OFF_BHH + g * SS + o];
            float a0 = lo32(acc0) + hi32(acc0) + bh;
            float a1 = lo32(acc1) + hi32(acc1) + bh;
            float a2 = lo32(acc2) + hi32(acc2) + bh;
            float a3 = lo32(acc3) + hi32(acc3) + bh;
            const int b0 = rg * 4;
            if (g < 2) {
                sm[OFF_S + g * 480 + (b0 + 0) * SS + o] = a0 + gi.x;
                sm[OFF_S + g * 480 + (b0 + 1) * SS + o] = a1 + gi.y;
                sm[OFF_S + g * 480 + (b0 + 2) * SS + o] = a2 + gi.z;
                sm[OFF_S + g * 480 + (b0 + 3) * SS + o] = a3 + gi.w;
            } else {
                sm[OFF_S + 2 * 480 + (b0 + 0) * SS + o] = a0;
                sm[OFF_S + 2 * 480 + (b0 + 1) * SS + o] = a1;
                sm[OFF_S + 2 * 480 + (b0 + 2) * SS + o] = a2;
                sm[OFF_S + 2 * 480 + (b0 + 3) * SS + o] = a3;
                sm[OFF_S + 3 * 480 + (b0 + 0) * SS + o] = gi.x;
                sm[OFF_S + 3 * 480 + (b0 + 1) * SS + o] = gi.y;
                sm[OFF_S + 3 * 480 + (b0 + 2) * SS + o] = gi.z;
                sm[OFF_S + 3 * 480 + (b0 + 3) * SS + o] = gi.w;
            }
        }
    } else if (loadNode >= 0) {
        for (int idx = t - 384; idx < 2 * ROWS * SEX; idx += 128) {
            int which = idx / 80;
            int loc = idx % 80;
            int b = loc / SEX, u = loc % SEX;
            const float* src = which ? dz : z;
            sm[(which ? OFF_DZI : OFF_ZI) + loc] =
                src[((size_t)(row0 + b)) * NN * SEX + (size_t)loadNode * SEX + u];
        }
    }
    __syncthreads();
    if (t < 480) {
        int b = t / SS, o2 = t - b * SS;
        float r  = sigm(sm[OFF_S + t]);
        float zg = sigm(sm[OFF_S + 480 + t]);
        float nv = tanh_f(fmaf(r, sm[OFF_S + 960 + t], sm[OFF_S + 1440 + t]));
        float hold = hz ? 0.f : sm[curBS + b * 64 + o2];
        float hnew = (1.f - zg) * nv + zg * hold;
        float blend = sm[OFF_HAS + b * 64 + node];
        float res = hold + blend * (hnew - hold);
        sm[nxtBS + b * 64 + o2] = res;
        sm[nxtSB + o2 * 9 + b] = res;
    }
    __syncthreads();
    hz = false;
}

// rho_i = act([h, z_i, dz_i] @ Wp^T + bp) -> smem RHO [o][8]. Wp from global (L2).
// hz==true means no edges ran: z/dz were NOT prestaged -> load here.
__device__ __forceinline__ void project(int node, const float* z, const float* dz,
                                        const float* Wp, bool isfwd, bool hz,
                                        int row0, int curSB)
{
    extern __shared__ float sm[];
    const int t = threadIdx.x;
    if (hz) {
        if (t < 2 * ROWS * SEX) {
            int which = t / 80;
            int loc = t % 80;
            int b = loc / SEX, u = loc % SEX;
            const float* src = which ? dz : z;
            sm[(which ? OFF_DZI : OFF_ZI) + loc] =
                src[((size_t)(row0 + b)) * NN * SEX + (size_t)node * SEX + u];
        }
        __syncthreads();
    }
    if (t < 480) {
        int o = t >> 3, b = t & 7;
        float acc = sm[OFF_BP + o];
        const float4* wrow = (const float4*)(Wp + o * 80);
        if (!hz) {
#pragma unroll
            for (int q = 0; q < 15; q++) {
                float4 w4 = wrow[q];
                acc = fmaf(w4.x, sm[curSB + (4 * q + 0) * 9 + b], acc);
                acc = fmaf(w4.y, sm[curSB + (4 * q + 1) * 9 + b], acc);
                acc = fmaf(w4.z, sm[curSB + (4 * q + 2) * 9 + b], acc);
                acc = fmaf(w4.w, sm[curSB + (4 * q + 3) * 9 + b], acc);
            }
        }
#pragma unroll
        for (int q = 0; q < 5; q++) {
            float4 w4 = wrow[15 + q];
            int u = 4 * q;
            float v0 = (u < SEX)     ? sm[OFF_ZI + b * SEX + u]     : sm[OFF_DZI + b * SEX + u - SEX];
            float v1 = (u + 1 < SEX) ? sm[OFF_ZI + b * SEX + u + 1] : sm[OFF_DZI + b * SEX + u + 1 - SEX];
            float v2 = (u + 2 < SEX) ? sm[OFF_ZI + b * SEX + u + 2] : sm[OFF_DZI + b * SEX + u + 2 - SEX];
            float v3 = (u + 3 < SEX) ? sm[OFF_ZI + b * SEX + u + 3] : sm[OFF_DZI + b * SEX + u + 3 - SEX];
            acc = fmaf(w4.x, v0, acc);
            acc = fmaf(w4.y, v1, acc);
            acc = fmaf(w4.z, v2, acc);
            acc = fmaf(w4.w, v3, acc);
        }
        sm[OFF_RHO + t] = isfwd ? tanh_f(acc) : acc;   // t == o*8+b
    }
    __syncthreads();
}

// gi (lanes 0..359, two row groups) + psi (lanes 360..373) in one step.
__device__ __forceinline__ void gi_psi_step(int node, float* gi4, float* psi_g,
                                            bool doGi, int row0, int bg)
{
    extern __shared__ float sm[];
    const int t = threadIdx.x;
    if (t < 360) {
        if (doGi) {
            int rg = t / 180, l = t - rg * 180;
            unsigned long long a01 = splat2(sm[OFF_BIH + l]);
            unsigned long long a23 = a01;
            const float4* wrow = (const float4*)&sm[OFF_WIH + l * SS];
#pragma unroll
            for (int q = 0; q < 15; q++) {
                float4 w4 = wrow[q];
                ulonglong2 r0 = *(const ulonglong2*)&sm[OFF_RHO + (4 * q + 0) * 8 + rg * 4];
                ulonglong2 r1 = *(const ulonglong2*)&sm[OFF_RHO + (4 * q + 1) * 8 + rg * 4];
                ulonglong2 r2 = *(const ulonglong2*)&sm[OFF_RHO + (4 * q + 2) * 8 + rg * 4];
                ulonglong2 r3 = *(const ulonglong2*)&sm[OFF_RHO + (4 * q + 3) * 8 + rg * 4];
                unsigned long long wx = splat2(w4.x), wy = splat2(w4.y);
                unsigned long long wz = splat2(w4.z), ww = splat2(w4.w);
                fma2(a01, wx, r0.x); fma2(a23, wx, r0.y);
                fma2(a01, wy, r1.x); fma2(a23, wy, r1.y);
                fma2(a01, wz, r2.x); fma2(a23, wz, r2.y);
                fma2(a01, ww, r3.x); fma2(a23, ww, r3.y);
            }
            int g = l / SS, o = l - g * SS;
            *(float4*)(gi4 + ((((size_t)node * NBG + bg) * 3 + g) * SS + o) * 8 + rg * 4) =
                make_float4(lo32(a01), hi32(a01), lo32(a23), hi32(a23));
        }
    } else if (t < 360 + 2 * NROLE) {
        int r = (t - 360) % NROLE, rg = (t - 360) / NROLE;
        unsigned long long a01 = 0, a23 = 0;
#pragma unroll 10
        for (int s = 0; s < SS; s++) {
            unsigned long long w = splat2(sm[OFF_WUH + r * SS + s]);
            ulonglong2 rr = *(const ulonglong2*)&sm[OFF_RHO + s * 8 + rg * 4];
            fma2(a01, w, rr.x);
            fma2(a23, w, rr.y);
        }
        int rb = row0 + rg * 4;
        psi_g[((size_t)(rb + 0) * NROLE + r) * NN + node] = lo32(a01);
        psi_g[((size_t)(rb + 1) * NROLE + r) * NN + node] = hi32(a01);
        psi_g[((size_t)(rb + 2) * NROLE + r) * NN + node] = lo32(a23);
        psi_g[((size_t)(rb + 3) * NROLE + r) * NN + node] = hi32(a23);
    }
    __syncthreads();
}

__global__ void __launch_bounds__(NT, 1)
phase1_kernel(const float* z, const float* dz, const float* has, const int* adj,
              const float* Wih_f, const float* Whh_f, const float* bih_f, const float* bhh_f,
              const float* Wih_b, const float* Whh_b, const float* bih_b, const float* bhh_b,
              const float* Wf, const float* bf, const float* Wb, const float* bb,
              const float* Wu)
{
    extern __shared__ float sm[];
    const int t = threadIdx.x;
    const int warp = t >> 5, lane = t & 31;
    const int bg = blockIdx.x;
    const int row0 = bg * ROWS;
    const int dir = blockIdx.y;

    const float* Whh = dir ? Whh_b : Whh_f;
    const float* Wih = dir ? Wih_b : Wih_f;
    const float* Wp  = dir ? Wb    : Wf;
    const float* bhh = dir ? bhh_b : bhh_f;
    const float* bih = dir ? bih_b : bih_f;
    const float* bp  = dir ? bb    : bf;
    float* gi4     = dir ? g_gi_b    : g_gi_f;
    float* alpha_g = dir ? g_alpha_b : g_alpha_f;
    float* psi_g   = dir ? g_psi_b   : g_psi_f;

    // 12 GEMM warps: rowgroup = warp/6, role6 = warp%6 -> gate, output half.
    // SMSP load: exactly 3 GEMM warps per SMSP, deterministic (1 CTA/SM).
    int rg = 0, g = 0, o = 0;
    bool gemmActive = false;
    if (warp < 12) {
        rg = warp / 6;
        int r6 = warp % 6;
        g = r6 % 3;
        o = (r6 / 3) * 32 + lane;
        gemmActive = (o < SS);
    }

    // Whh row for this lane in registers (30 f32x2 pairs over s).
    unsigned long long wp[30];
    if (gemmActive) {
        const float* wsrc = Whh + ((size_t)g * SS + o) * SS;
#pragma unroll
        for (int q = 0; q < 30; q++)
            wp[q] = *(const unsigned long long*)(wsrc + 2 * q);
    }

    // ---- stage smem ----
    for (int idx = t; idx < GG * SS; idx += NT) sm[OFF_WIH + idx] = Wih[idx];
    for (int idx = t; idx < GG; idx += NT) {
        sm[OFF_BIH + idx] = bih[idx];
        sm[OFF_BHH + idx] = bhh[idx];
    }
    if (t < SS) sm[OFF_BP + t] = bp[t];
    for (int idx = t; idx < ROWS * NN; idx += NT)
        sm[OFF_HAS + idx] = has[(size_t)(row0 + idx / NN) * NN + (idx % NN)];
    for (int idx = t; idx < NROLE * SS; idx += NT) {
        int r = idx / SS, s = idx % SS;
        sm[OFF_WUH + idx] = Wu[r * 2 * SS + dir * SS + s];
    }
    if (t < NN) {
        unsigned long long pm = 0ull, sk = 0ull;
        for (int j = 0; j < NN; j++) {
            if (adj[j * NN + t]) pm |= 1ull << j;   // predecessors of t
            if (adj[t * NN + j]) sk |= 1ull << j;   // successors of t
        }
        ((unsigned long long*)&sm[OFF_MASK])[t] = dir ? sk : pm;
        bool need = dir ? (pm != 0ull || t < II) : (sk != 0ull || t >= NN - OO);
        ((int*)&sm[OFF_NEED])[t] = need ? 1 : 0;
    }
    __syncthreads();

    const unsigned long long* mask = (const unsigned long long*)&sm[OFF_MASK];
    const int* need = (const int*)&sm[OFF_NEED];

    int curBS = OFF_HBS0, nxtBS = OFF_HBS1;
    int curSB = OFF_HSB0, nxtSB = OFF_HSB1;

    // ---- DAG pass ----
    for (int k = 0; k < NN; k++) {
        const int i = dir ? NN - 1 - k : k;
        bool hz = true;
        unsigned long long m = mask[i];
        bool first = true;
        while (m) {
            int j;
            if (dir) { j = 63 - __clzll((long long)m); m &= ~(1ull << j); }   // descending
            else     { j = __ffsll((long long)m) - 1;  m &= m - 1; }          // ascending
            gru_step(j, gi4, hz, bg, gemmActive, g, o, rg, wp,
                     curBS, nxtBS, nxtSB, first ? i : -1, z, dz, row0);
            int tb = curBS; curBS = nxtBS; nxtBS = tb;
            int ts = curSB; curSB = nxtSB; nxtSB = ts;
            first = false;
        }
        project(i, z, dz, Wp, dir == 0, hz, row0, curSB);
        gi_psi_step(i, gi4, psi_g, need[i] != 0, row0, bg);
    }

    // ---- alpha scan ----
    {
        bool hz = true;
        for (int k2 = 0; k2 < OO; k2++) {
            int an = dir ? (II - 1 - k2) : (NN - OO + k2);
            gru_step(an, gi4, hz, bg, gemmActive, g, o, rg, wp,
                     curBS, nxtBS, nxtSB, -1, z, dz, row0);
            int tb = curBS; curBS = nxtBS; nxtBS = tb;
            int ts = curSB; curSB = nxtSB; nxtSB = ts;
        }
        if (t < 480) {
            int o2 = t >> 3, b = t & 7;
            alpha_g[(size_t)(row0 + b) * SS + o2] = sm[curSB + o2 * 9 + b];
        }
    }
}

// ---- phase 2: heads + psi assembly + softmaxes ----
#define P2NT 256
#define P2_AF 0
#define P2_AB 480
#define P2_HAS 960
#define P2_OMG 1472
#define P2_PSI 1536
#define P2_FLOATS (P2_PSI + ROWS * NROLE * NN)

__global__ void __launch_bounds__(P2NT)
phase2_kernel(const float* has, const float* Wa, const float* ba,
              const float* Wc, const float* bc, const float* bu,
              float* out)
{
    __shared__ float s2[P2_FLOATS];
    const int t = threadIdx.x;
    const int row0 = blockIdx.x * ROWS;

    for (int idx = t; idx < SS * ROWS; idx += P2NT) {
        int s = idx >> 3, b = idx & 7;
        s2[P2_AF + idx] = g_alpha_f[(size_t)(row0 + b) * SS + s];
        s2[P2_AB + idx] = g_alpha_b[(size_t)(row0 + b) * SS + s];
    }
    for (int idx = t; idx < ROWS * NN; idx += P2NT)
        s2[P2_HAS + idx] = has[(size_t)(row0 + idx / NN) * NN + (idx % NN)];
    __syncthreads();

    if (t < ROWS * NACT) {
        int b = t / NACT, a = t % NACT;
        float acc = ba[a];
#pragma unroll
        for (int s = 0; s < SS; s++) {
            acc = fmaf(Wa[a * 2 * SS + s],      s2[P2_AF + s * 8 + b], acc);
            acc = fmaf(Wa[a * 2 * SS + SS + s], s2[P2_AB + s * 8 + b], acc);
        }
        s2[P2_OMG + t] = acc;
    } else if (t < ROWS * NACT + ROWS) {
        int b = t - ROWS * NACT;
        float acc = bc[0];
#pragma unroll
        for (int s = 0; s < SS; s++) {
            acc = fmaf(Wc[s],      s2[P2_AF + s * 8 + b], acc);
            acc = fmaf(Wc[SS + s], s2[P2_AB + s * 8 + b], acc);
        }
        out[(size_t)BATCH * NACT + (size_t)BATCH * NROLE * NN + row0 + b] = acc;
    }

    for (int idx = t; idx < ROWS * NROLE * NN; idx += P2NT) {
        int n = idx % NN;
        int r = (idx / NN) % NROLE;
        int b = idx / (NROLE * NN);
        size_t gg = ((size_t)(row0 + b) * NROLE + r) * NN + n;
        float v = g_psi_f[gg] + g_psi_b[gg] + bu[r];
        float m = s2[P2_HAS + b * NN + n];
        s2[P2_PSI + idx] = m * v - 60.f * (1.f - m);
    }
    __syncthreads();

    if (t < ROWS) {
        float mx = -1e30f;
        for (int a = 0; a < NACT; a++) mx = fmaxf(mx, s2[P2_OMG + t * NACT + a]);
        float e[NACT], ssum = 0.f;
        for (int a = 0; a < NACT; a++) {
            e[a] = __expf(s2[P2_OMG + t * NACT + a] - mx);
            ssum += e[a];
        }
        float inv = __fdividef(1.f, ssum);
        for (int a = 0; a < NACT; a++) out[(size_t)(row0 + t) * NACT + a] = e[a] * inv;
    }

    for (int p0 = t; p0 < ROWS * NROLE; p0 += P2NT) {
        int b = p0 / NROLE, r = p0 % NROLE;
        float* rowp = &s2[P2_PSI + (b * NROLE + r) * NN];
        float mx = -1e30f;
        for (int n = 0; n < NN; n++) mx = fmaxf(mx, rowp[n]);
        float ssum = 0.f;
        for (int n = 0; n < NN; n++) { float e = __expf(rowp[n] - mx); rowp[n] = e; ssum += e; }
        float inv = __fdividef(1.f, ssum);
        float* op = out + (size_t)BATCH * NACT + (size_t)(row0 + b) * NROLE * NN + (size_t)r * NN;
        for (int n = 0; n < NN; n++) op[n] = rowp[n] * inv;
    }
}

extern "C" void kernel_launch(void* const* d_in, const int* in_sizes, int n_in,
                              void* d_out, int out_size)
{
    cudaFuncSetAttribute(phase1_kernel, cudaFuncAttributeMaxDynamicSharedMemorySize, SMEM_BYTES);
    dim3 grid1(NBG, 2);
    phase1_kernel<<<grid1, NT, SMEM_BYTES>>>(
        (const float*)d_in[0], (const float*)d_in[1], (const float*)d_in[2], (const int*)d_in[3],
        (const float*)d_in[4], (const float*)d_in[5], (const float*)d_in[6], (const float*)d_in[7],
        (const float*)d_in[8], (const float*)d_in[9], (const float*)d_in[10], (const float*)d_in[11],
        (const float*)d_in[12], (const float*)d_in[13], (const float*)d_in[14], (const float*)d_in[15],
        (const float*)d_in[20]);
    phase2_kernel<<<NBG, P2NT>>>(
        (const float*)d_in[2],
        (const float*)d_in[16], (const float*)d_in[17], (const float*)d_in[18], (const float*)d_in[19],
        (const float*)d_in[21], (float*)d_out);
}

// round 17
// speedup vs baseline: 1.5652x; 1.5652x over previous
#include <cuda_runtime.h>

#define NN 64
#define SS 60
#define GG 180
#define BATCH 512
#define SEX 10
#define ROWS 4
#define NT 256
#define NBG (BATCH / ROWS)
#define NACT 5
#define NROLE 7
#define OO 8
#define II 8

// ---- phase-1 shared memory layout (float offsets) ----
#define OFF_WIH  0          // 180*60
#define OFF_BIH  10800      // 180
#define OFF_BHH  10980      // 180 [g*60+o]
#define OFF_BP   11160      // 60
#define OFF_HAS  11220      // [b][64] = 256
#define OFF_MASK 11476      // 64 ull = 128 floats
#define OFF_NEED 11604      // 64
#define OFF_WUH  11668      // 7*60
#define OFF_HBS0 12088      // H ping  [b][64]
#define OFF_HBS1 12344      // H pong  [b][64]
#define OFF_HSB0 12600      // H ping  [s][4]
#define OFF_HSB1 12840      // H pong  [s][4]
#define OFF_S    13080      // 4 x [b*60+o] = 960  (r, z, nA, nG)
#define OFF_RHO  14040      // [s][4]
#define OFF_ZI   14280
#define OFF_DZI  14320
#define SMEM_FLOATS 14360
#define SMEM_BYTES (SMEM_FLOATS * 4)

// ---- global scratch ----
// gi layout: [node][bg][gate][o][4 rows]
__device__ float g_gi_f[(size_t)NN * NBG * 3 * SS * 4];
__device__ float g_gi_b[(size_t)NN * NBG * 3 * SS * 4];
__device__ float g_alpha_f[(size_t)BATCH * SS];
__device__ float g_alpha_b[(size_t)BATCH * SS];
__device__ float g_psi_f[(size_t)BATCH * NROLE * NN];
__device__ float g_psi_b[(size_t)BATCH * NROLE * NN];

__device__ __forceinline__ float sigm(float x) {
    return __fdividef(1.f, 1.f + __expf(-x));
}
__device__ __forceinline__ float tanh_f(float x) {
    float e = __expf(2.f * x);
    return 1.f - __fdividef(2.f, e + 1.f);
}
__device__ __forceinline__ void fma2(unsigned long long& d, unsigned long long a,
                                     unsigned long long b) {
    asm("fma.rn.f32x2 %0, %1, %2, %0;" : "+l"(d) : "l"(a), "l"(b));
}
__device__ __forceinline__ unsigned long long splat2(float w) {
    unsigned long long r;
    asm("mov.b64 %0, {%1, %1};" : "=l"(r) : "f"(w));
    return r;
}
__device__ __forceinline__ float lo32(unsigned long long v) {
    return __uint_as_float((unsigned)v);
}
__device__ __forceinline__ float hi32(unsigned long long v) {
    return __uint_as_float((unsigned)(v >> 32));
}

// One GRU edge step: gate-split GEMM (6 warps, weights in regs) + exchange + act.
// gi: this lane's pre-loaded gi float4 (software-pipelined by the caller).
__device__ __forceinline__ void gru_step(int node, float4 gi, bool& hz,
                                         bool gemmActive, int g, int o,
                                         const unsigned long long* wp,
                                         int curBS, int nxtBS, int nxtSB)
{
    extern __shared__ float sm[];
    const int t = threadIdx.x;
    if (gemmActive) {
        unsigned long long acc0 = 0, acc1 = 0, acc2 = 0, acc3 = 0;
        if (!hz) {
#pragma unroll
            for (int q = 0; q < 15; q++) {
                ulonglong2 h0 = *(const ulonglong2*)&sm[curBS + 0 * 64 + 4 * q];
                ulonglong2 h1 = *(const ulonglong2*)&sm[curBS + 1 * 64 + 4 * q];
                ulonglong2 h2 = *(const ulonglong2*)&sm[curBS + 2 * 64 + 4 * q];
                ulonglong2 h3 = *(const ulonglong2*)&sm[curBS + 3 * 64 + 4 * q];
                fma2(acc0, wp[2 * q], h0.x); fma2(acc0, wp[2 * q + 1], h0.y);
                fma2(acc1, wp[2 * q], h1.x); fma2(acc1, wp[2 * q + 1], h1.y);
                fma2(acc2, wp[2 * q], h2.x); fma2(acc2, wp[2 * q + 1], h2.y);
                fma2(acc3, wp[2 * q], h3.x); fma2(acc3, wp[2 * q + 1], h3.y);
            }
        }
        float bh = sm[OFF_BHH + g * SS + o];
        float a0 = lo32(acc0) + hi32(acc0) + bh;
        float a1 = lo32(acc1) + hi32(acc1) + bh;
        float a2 = lo32(acc2) + hi32(acc2) + bh;
        float a3 = lo32(acc3) + hi32(acc3) + bh;
        if (g < 2) {
            sm[OFF_S + g * 240 + 0 * 60 + o] = a0 + gi.x;
            sm[OFF_S + g * 240 + 1 * 60 + o] = a1 + gi.y;
            sm[OFF_S + g * 240 + 2 * 60 + o] = a2 + gi.z;
            sm[OFF_S + g * 240 + 3 * 60 + o] = a3 + gi.w;
        } else {
            sm[OFF_S + 2 * 240 + 0 * 60 + o] = a0;
            sm[OFF_S + 2 * 240 + 1 * 60 + o] = a1;
            sm[OFF_S + 2 * 240 + 2 * 60 + o] = a2;
            sm[OFF_S + 2 * 240 + 3 * 60 + o] = a3;
            sm[OFF_S + 3 * 240 + 0 * 60 + o] = gi.x;
            sm[OFF_S + 3 * 240 + 1 * 60 + o] = gi.y;
            sm[OFF_S + 3 * 240 + 2 * 60 + o] = gi.z;
            sm[OFF_S + 3 * 240 + 3 * 60 + o] = gi.w;
        }
    }
    __syncthreads();
    if (t < 240) {
        int b = t / 60, o2 = t % 60;
        float r  = sigm(sm[OFF_S + 0 * 240 + t]);
        float zg = sigm(sm[OFF_S + 1 * 240 + t]);
        float nv = tanh_f(fmaf(r, sm[OFF_S + 2 * 240 + t], sm[OFF_S + 3 * 240 + t]));
        float hold = hz ? 0.f : sm[curBS + b * 64 + o2];
        float hnew = (1.f - zg) * nv + zg * hold;
        float blend = sm[OFF_HAS + b * 64 + node];
        float res = hold + blend * (hnew - hold);
        sm[nxtBS + b * 64 + o2] = res;
        sm[nxtSB + o2 * 4 + b] = res;
    }
    __syncthreads();
    hz = false;
}

// rho_i = act([h, z_i, dz_i] @ Wp^T + bp) -> smem RHO [s][4]. Wp from global.
__device__ __forceinline__ void project(int node, const float* z, const float* dz,
                                        const float* Wp, bool isfwd, bool hz,
                                        int row0, int curSB)
{
    extern __shared__ float sm[];
    const int t = threadIdx.x;
    if (t < 2 * ROWS * SEX) {
        int which = t / 40;
        int loc = t % 40;
        int b = loc / SEX, u = loc % SEX;
        const float* src = which ? dz : z;
        sm[(which ? OFF_DZI : OFF_ZI) + loc] =
            src[((size_t)(row0 + b)) * NN * SEX + (size_t)node * SEX + u];
    }
    __syncthreads();
    if (t < SS * ROWS) {
        int o = t >> 2, b = t & 3;
        float acc = sm[OFF_BP + o];
        const float4* wrow = (const float4*)(Wp + o * 80);
        if (!hz) {
#pragma unroll
            for (int q = 0; q < SS / 4; q++) {
                float4 w4 = wrow[q];
                acc = fmaf(w4.x, sm[curSB + (4 * q + 0) * 4 + b], acc);
                acc = fmaf(w4.y, sm[curSB + (4 * q + 1) * 4 + b], acc);
                acc = fmaf(w4.z, sm[curSB + (4 * q + 2) * 4 + b], acc);
                acc = fmaf(w4.w, sm[curSB + (4 * q + 3) * 4 + b], acc);
            }
        }
#pragma unroll
        for (int q = 0; q < (2 * SEX) / 4; q++) {
            float4 w4 = wrow[SS / 4 + q];
            int u = 4 * q;
            float v0 = (u < SEX)     ? sm[OFF_ZI + b * SEX + u]     : sm[OFF_DZI + b * SEX + u - SEX];
            float v1 = (u + 1 < SEX) ? sm[OFF_ZI + b * SEX + u + 1] : sm[OFF_DZI + b * SEX + u + 1 - SEX];
            float v2 = (u + 2 < SEX) ? sm[OFF_ZI + b * SEX + u + 2] : sm[OFF_DZI + b * SEX + u + 2 - SEX];
            float v3 = (u + 3 < SEX) ? sm[OFF_ZI + b * SEX + u + 3] : sm[OFF_DZI + b * SEX + u + 3 - SEX];
            acc = fmaf(w4.x, v0, acc);
            acc = fmaf(w4.y, v1, acc);
            acc = fmaf(w4.z, v2, acc);
            acc = fmaf(w4.w, v3, acc);
        }
        sm[OFF_RHO + t] = isfwd ? tanh_f(acc) : acc;
    }
    __syncthreads();
}

// gi (lanes 0..179, gate-major layout) + psi (lanes 180..186).
__device__ __forceinline__ void gi_psi_step(int node, float* gi4, float* psi_g,
                                            bool doGi, int row0, int bg)
{
    extern __shared__ float sm[];
    const int t = threadIdx.x;
    if (t < GG) {
        if (doGi) {
            unsigned long long a01 = splat2(sm[OFF_BIH + t]);
            unsigned long long a23 = a01;
            const float4* wrow = (const float4*)&sm[OFF_WIH + t * SS];
#pragma unroll
            for (int q = 0; q < SS / 4; q++) {
                float4 w4 = wrow[q];
                ulonglong2 r0 = *(const ulonglong2*)&sm[OFF_RHO + (4 * q + 0) * 4];
                ulonglong2 r1 = *(const ulonglong2*)&sm[OFF_RHO + (4 * q + 1) * 4];
                ulonglong2 r2 = *(const ulonglong2*)&sm[OFF_RHO + (4 * q + 2) * 4];
                ulonglong2 r3 = *(const ulonglong2*)&sm[OFF_RHO + (4 * q + 3) * 4];
                unsigned long long wx = splat2(w4.x), wy = splat2(w4.y);
                unsigned long long wz = splat2(w4.z), ww = splat2(w4.w);
                fma2(a01, wx, r0.x); fma2(a23, wx, r0.y);
                fma2(a01, wy, r1.x); fma2(a23, wy, r1.y);
                fma2(a01, wz, r2.x); fma2(a23, wz, r2.y);
                fma2(a01, ww, r3.x); fma2(a23, ww, r3.y);
            }
            int g = t / SS, o = t % SS;
            float4* dst = (float4*)(gi4 + ((((size_t)node * NBG + bg) * 3 + g) * SS + o) * 4);
            *dst = make_float4(lo32(a01), hi32(a01), lo32(a23), hi32(a23));
        }
    } else if (t < GG + NROLE) {
        int r = t - GG;
        unsigned long long a01 = 0, a23 = 0;
#pragma unroll 10
        for (int s = 0; s < SS; s++) {
            unsigned long long w = splat2(sm[OFF_WUH + r * SS + s]);
            ulonglong2 rr = *(const ulonglong2*)&sm[OFF_RHO + s * 4];
            fma2(a01, w, rr.x);
            fma2(a23, w, rr.y);
        }
        psi_g[((size_t)(row0 + 0) * NROLE + r) * NN + node] = lo32(a01);
        psi_g[((size_t)(row0 + 1) * NROLE + r) * NN + node] = hi32(a01);
        psi_g[((size_t)(row0 + 2) * NROLE + r) * NN + node] = lo32(a23);
        psi_g[((size_t)(row0 + 3) * NROLE + r) * NN + node] = hi32(a23);
    }
    __syncthreads();
}

__global__ void __launch_bounds__(NT, 2)
phase1_kernel(const float* z, const float* dz, const float* has, const int* adj,
              const float* Wih_f, const float* Whh_f, const float* bih_f, const float* bhh_f,
              const float* Wih_b, const float* Whh_b, const float* bih_b, const float* bhh_b,
              const float* Wf, const float* bf, const float* Wb, const float* bb,
              const float* Wu)
{
    extern __shared__ float sm[];
    const int t = threadIdx.x;
    const int warp = t >> 5, lane = t & 31;
    const int bg = blockIdx.x;
    const int row0 = bg * ROWS;
    const int dir = blockIdx.y;

    const float* Whh = dir ? Whh_b : Whh_f;
    const float* Wih = dir ? Wih_b : Wih_f;
    const float* Wp  = dir ? Wb    : Wf;
    const float* bhh = dir ? bhh_b : bhh_f;
    const float* bih = dir ? bih_b : bih_f;
    const float* bp  = dir ? bb    : bf;
    float* gi4     = dir ? g_gi_b    : g_gi_f;
    float* alpha_g = dir ? g_alpha_b : g_alpha_f;
    float* psi_g   = dir ? g_psi_b   : g_psi_f;

    // GEMM warp role: fwd uses warps {0,1,2,3,4,7}; bwd uses {0,1,2,3,5,6}
    // -> 3 GEMM warps per SMSP when fwd+bwd CTAs co-reside.
    int role;
    if (dir == 0) role = (warp < 5) ? warp : (warp == 7 ? 5 : -1);
    else          role = (warp < 4) ? warp : (warp == 5 ? 4 : (warp == 6 ? 5 : -1));
    const int g = (role >= 0) ? role % 3 : 0;
    const int o = (role >= 0) ? (role / 3) * 32 + lane : 0;
    const bool gemmActive = (role >= 0) && (o < SS);

    // Whh row for this lane in registers (30 x f32x2 pairs over s).
    unsigned long long wp[30];
    if (gemmActive) {
        const float* wsrc = Whh + ((size_t)g * SS + o) * SS;
#pragma unroll
        for (int q = 0; q < 30; q++)
            wp[q] = *(const unsigned long long*)(wsrc + 2 * q);
    }
    // per-lane gi base for pipelined loads
    const float* giLane = gi4 + (((size_t)bg * 3 + g) * SS + o) * 4;
    const size_t giNodeStride = (size_t)NBG * 3 * SS * 4;

    // ---- stage smem ----
    for (int idx = t; idx < GG * SS; idx += NT) sm[OFF_WIH + idx] = Wih[idx];
    for (int idx = t; idx < GG; idx += NT) {
        sm[OFF_BIH + idx] = bih[idx];
        sm[OFF_BHH + idx] = bhh[idx];
    }
    if (t < SS) sm[OFF_BP + t] = bp[t];
    for (int idx = t; idx < ROWS * NN; idx += NT)
        sm[OFF_HAS + idx] = has[(size_t)(row0 + idx / NN) * NN + (idx % NN)];
    for (int idx = t; idx < NROLE * SS; idx += NT) {
        int r = idx / SS, s = idx % SS;
        sm[OFF_WUH + idx] = Wu[r * 2 * SS + dir * SS + s];
    }
    if (t < NN) {
        unsigned long long pm = 0ull, sk = 0ull;
        for (int j = 0; j < NN; j++) {
            if (adj[j * NN + t]) pm |= 1ull << j;   // predecessors of t
            if (adj[t * NN + j]) sk |= 1ull << j;   // successors of t
        }
        ((unsigned long long*)&sm[OFF_MASK])[t] = dir ? sk : pm;
        bool need = dir ? (pm != 0ull || t < II) : (sk != 0ull || t >= NN - OO);
        ((int*)&sm[OFF_NEED])[t] = need ? 1 : 0;
    }
    __syncthreads();

    const unsigned long long* mask = (const unsigned long long*)&sm[OFF_MASK];
    const int* need = (const int*)&sm[OFF_NEED];

    int curBS = OFF_HBS0, nxtBS = OFF_HBS1;
    int curSB = OFF_HSB0, nxtSB = OFF_HSB1;

    // ---- DAG pass (gi loads software-pipelined one edge ahead) ----
    for (int k = 0; k < NN; k++) {
        const int i = dir ? NN - 1 - k : k;
        bool hz = true;
        unsigned long long m = mask[i];

        int jCur = -1;
        float4 giCur = make_float4(0.f, 0.f, 0.f, 0.f);
        if (m) {
            if (dir) { jCur = 63 - __clzll((long long)m); m &= ~(1ull << jCur); }
            else     { jCur = __ffsll((long long)m) - 1;  m &= m - 1; }
            if (gemmActive) giCur = *(const float4*)(giLane + (size_t)jCur * giNodeStride);
        }
        while (jCur >= 0) {
            int jNxt = -1;
            if (m) {
                if (dir) { jNxt = 63 - __clzll((long long)m); m &= ~(1ull << jNxt); }
                else     { jNxt = __ffsll((long long)m) - 1;  m &= m - 1; }
            }
            float4 giNxt = make_float4(0.f, 0.f, 0.f, 0.f);
            if (jNxt >= 0 && gemmActive)   // issued BEFORE this step's barriers
                giNxt = *(const float4*)(giLane + (size_t)jNxt * giNodeStride);
            gru_step(jCur, giCur, hz, gemmActive, g, o, wp, curBS, nxtBS, nxtSB);
            int tb = curBS; curBS = nxtBS; nxtBS = tb;
            int ts = curSB; curSB = nxtSB; nxtSB = ts;
            jCur = jNxt; giCur = giNxt;
        }
        project(i, z, dz, Wp, dir == 0, hz, row0, curSB);
        gi_psi_step(i, gi4, psi_g, need[i] != 0, row0, bg);
    }

    // ---- alpha scan (same pipelining; node sequence is known) ----
    {
        bool hz = true;
        int an0 = dir ? (II - 1) : (NN - OO);
        float4 giCur = make_float4(0.f, 0.f, 0.f, 0.f);
        if (gemmActive) giCur = *(const float4*)(giLane + (size_t)an0 * giNodeStride);
        for (int k2 = 0; k2 < OO; k2++) {
            int an = dir ? (II - 1 - k2) : (NN - OO + k2);
            float4 giNxt = make_float4(0.f, 0.f, 0.f, 0.f);
            if (k2 + 1 < OO && gemmActive) {
                int an2 = dir ? (II - 2 - k2) : (NN - OO + k2 + 1);
                giNxt = *(const float4*)(giLane + (size_t)an2 * giNodeStride);
            }
            gru_step(an, giCur, hz, gemmActive, g, o, wp, curBS, nxtBS, nxtSB);
            int tb = curBS; curBS = nxtBS; nxtBS = tb;
            int ts = curSB; curSB = nxtSB; nxtSB = ts;
            giCur = giNxt;
        }
        if (t < SS * ROWS) {
            int o2 = t >> 2, b = t & 3;
            alpha_g[(size_t)(row0 + b) * SS + o2] = sm[curSB + t];
        }
    }
}

// ---- phase 2: heads + psi assembly + softmaxes (tiny) ----
#define P2NT 192
#define P2_AF 0
#define P2_AB 240
#define P2_HAS 480
#define P2_OMG 736
#define P2_PSI 768
#define P2_FLOATS (P2_PSI + ROWS * NROLE * NN)

__global__ void __launch_bounds__(P2NT)
phase2_kernel(const float* has, const float* Wa, const float* ba,
              const float* Wc, const float* bc, const float* bu,
              float* out)
{
    __shared__ float s2[P2_FLOATS];
    const int t = threadIdx.x;
    const int row0 = blockIdx.x * ROWS;

    for (int idx = t; idx < SS * ROWS; idx += P2NT) {
        int s = idx >> 2, b = idx & 3;
        s2[P2_AF + idx] = g_alpha_f[(size_t)(row0 + b) * SS + s];
        s2[P2_AB + idx] = g_alpha_b[(size_t)(row0 + b) * SS + s];
    }
    for (int idx = t; idx < ROWS * NN; idx += P2NT)
        s2[P2_HAS + idx] = has[(size_t)(row0 + idx / NN) * NN + (idx % NN)];
    __syncthreads();

    if (t < ROWS * NACT) {
        int b = t / NACT, a = t % NACT;
        float acc = ba[a];
#pragma unroll
        for (int s = 0; s < SS; s++) {
            acc = fmaf(Wa[a * 2 * SS + s],      s2[P2_AF + s * 4 + b], acc);
            acc = fmaf(Wa[a * 2 * SS + SS + s], s2[P2_AB + s * 4 + b], acc);
        }
        s2[P2_OMG + t] = acc;
    } else if (t < ROWS * NACT + ROWS) {
        int b = t - ROWS * NACT;
        float acc = bc[0];
#pragma unroll
        for (int s = 0; s < SS; s++) {
            acc = fmaf(Wc[s],      s2[P2_AF + s * 4 + b], acc);
            acc = fmaf(Wc[SS + s], s2[P2_AB + s * 4 + b], acc);
        }
        out[(size_t)BATCH * NACT + (size_t)BATCH * NROLE * NN + row0 + b] = acc;
    }

    for (int idx = t; idx < ROWS * NROLE * NN; idx += P2NT) {
        int n = idx % NN;
        int r = (idx / NN) % NROLE;
        int b = idx / (NROLE * NN);
        size_t gg = ((size_t)(row0 + b) * NROLE + r) * NN + n;
        float v = g_psi_f[gg] + g_psi_b[gg] + bu[r];
        float m = s2[P2_HAS + b * NN + n];
        s2[P2_PSI + idx] = m * v - 60.f * (1.f - m);
    }
    __syncthreads();

    if (t < ROWS) {
        float mx = -1e30f;
        for (int a = 0; a < NACT; a++) mx = fmaxf(mx, s2[P2_OMG + t * NACT + a]);
        float e[NACT], ssum = 0.f;
        for (int a = 0; a < NACT; a++) {
            e[a] = __expf(s2[P2_OMG + t * NACT + a] - mx);
            ssum += e[a];
        }
        float inv = __fdividef(1.f, ssum);
        for (int a = 0; a < NACT; a++) out[(size_t)(row0 + t) * NACT + a] = e[a] * inv;
    }

    for (int p0 = t; p0 < ROWS * NROLE; p0 += P2NT) {
        int b = p0 / NROLE, r = p0 % NROLE;
        float* rowp = &s2[P2_PSI + (b * NROLE + r) * NN];
        float mx = -1e30f;
        for (int n = 0; n < NN; n++) mx = fmaxf(mx, rowp[n]);
        float ssum = 0.f;
        for (int n = 0; n < NN; n++) { float e = __expf(rowp[n] - mx); rowp[n] = e; ssum += e; }
        float inv = __fdividef(1.f, ssum);
        float* op = out + (size_t)BATCH * NACT + (size_t)(row0 + b) * NROLE * NN + (size_t)r * NN;
        for (int n = 0; n < NN; n++) op[n] = rowp[n] * inv;
    }
}

extern "C" void kernel_launch(void* const* d_in, const int* in_sizes, int n_in,
                              void* d_out, int out_size)
{
    cudaFuncSetAttribute(phase1_kernel, cudaFuncAttributeMaxDynamicSharedMemorySize, SMEM_BYTES);
    dim3 grid1(NBG, 2);
    phase1_kernel<<<grid1, NT, SMEM_BYTES>>>(
        (const float*)d_in[0], (const float*)d_in[1], (const float*)d_in[2], (const int*)d_in[3],
        (const float*)d_in[4], (const float*)d_in[5], (const float*)d_in[6], (const float*)d_in[7],
        (const float*)d_in[8], (const float*)d_in[9], (const float*)d_in[10], (const float*)d_in[11],
        (const float*)d_in[12], (const float*)d_in[13], (const float*)d_in[14], (const float*)d_in[15],
        (const float*)d_in[20]);
    phase2_kernel<<<NBG, P2NT>>>(
        (const float*)d_in[2],
        (const float*)d_in[16], (const float*)d_in[17], (const float*)d_in[18], (const float*)d_in[19],
        (const float*)d_in[21], (float*)d_out);
}